// round 13
// baseline (speedup 1.0000x reference)
#include <cuda_runtime.h>
#include <cuda_fp16.h>
#include <cstdint>

#define BB 128   // batch    (GEMM M)
#define LL 512   // lookback (GEMM K)
#define CC 512   // channels
#define FF 192   // forecast (GEMM N)

// A (nx = x - norm) in fp16 mma-fragment order:
// [c][ks16(32)][mtile(8)][lane(32)][8 halves]  -> 128KB/channel
__device__ __half g_packed[(size_t)CC * BB * LL];
// GEMM output staged coalesced per channel: [c][b][f]
__device__ float g_outp[(size_t)CC * BB * FF];

// ------------------------------------------------------------------ helpers
static __device__ __forceinline__ uint32_t smem_u32(const void* p) {
  uint32_t a;
  asm("{ .reg .u64 t; cvta.to.shared.u64 t, %1; cvt.u32.u64 %0, t; }" : "=r"(a) : "l"(p));
  return a;
}
static __device__ __forceinline__ void cp16(uint32_t dst, const void* src) {
  asm volatile("cp.async.cg.shared.global [%0], [%1], 16;" :: "r"(dst), "l"(src) : "memory");
}
// pack two floats into f16x2 (lo = first arg)
static __device__ __forceinline__ uint32_t pk2(float lo, float hi) {
  uint32_t r;
  asm("cvt.rn.f16x2.f32 %0, %1, %2;" : "=r"(r) : "f"(hi), "f"(lo));
  return r;
}
static __device__ __forceinline__ void mma16(float* d, const uint4& a, uint32_t b0, uint32_t b1) {
  asm volatile(
      "mma.sync.aligned.m16n8k16.row.col.f32.f16.f16.f32 "
      "{%0,%1,%2,%3}, {%4,%5,%6,%7}, {%8,%9}, {%0,%1,%2,%3};"
      : "+f"(d[0]), "+f"(d[1]), "+f"(d[2]), "+f"(d[3])
      : "r"(a.x), "r"(a.y), "r"(a.z), "r"(a.w), "r"(b0), "r"(b1));
}

// ------------------------------------------------------------------ pass 1
// m16n8k16 A-fragment: a0=(g, 2tg..2tg+1), a1=(g+8, 2tg..), a2=(g, 8+2tg..),
// a3=(g+8, 8+2tg..); lane = g*4+tg. Tile: 32 ch x 16 batch x 16 lookback.
__global__ void __launch_bounds__(256) pack_kernel(const float* __restrict__ x, int c_base) {
  __shared__ float xs[15 * 577 + 15 * 36 + 32 + 1];  // [l]*577 + [b]*36 + c
  __shared__ float nrm[16][32];
  const int t  = threadIdx.x;
  const int c0 = c_base + blockIdx.x * 32;
  const int b0 = blockIdx.y * 16;
  const int l0 = blockIdx.z * 16;

  if (t < 128) {
    int b = t >> 3, sg = t & 7;
    float4 v = *(const float4*)(x + ((size_t)(b0 + b) * LL + (LL - 1)) * CC + c0 + sg * 4);
    *(float4*)&nrm[b][sg * 4] = v;
  }
  __syncthreads();

#pragma unroll
  for (int i = 0; i < 8; i++) {
    int id = t + 256 * i;
    int row = id >> 3, sg = id & 7;
    int b = row >> 4, l = row & 15;
    float4 v = *(const float4*)(x + ((size_t)(b0 + b) * LL + l0 + l) * CC + c0 + sg * 4);
    float4 n = *(float4*)&nrm[b][sg * 4];
    int base = l * 577 + b * 36 + sg * 4;
    xs[base + 0] = v.x - n.x;
    xs[base + 1] = v.y - n.y;
    xs[base + 2] = v.z - n.z;
    xs[base + 3] = v.w - n.w;
  }
  __syncthreads();

  const int wid = t >> 5, lane = t & 31;
  const int g = lane >> 2, tg = lane & 3;
#pragma unroll
  for (int it = 0; it < 4; it++) {
    int c = wid * 4 + it;
    uint4 v;
    v.x = pk2(xs[(2 * tg)     * 577 + g       * 36 + c], xs[(2 * tg + 1) * 577 + g       * 36 + c]);
    v.y = pk2(xs[(2 * tg)     * 577 + (g + 8) * 36 + c], xs[(2 * tg + 1) * 577 + (g + 8) * 36 + c]);
    v.z = pk2(xs[(8 + 2 * tg) * 577 + g       * 36 + c], xs[(9 + 2 * tg) * 577 + g       * 36 + c]);
    v.w = pk2(xs[(8 + 2 * tg) * 577 + (g + 8) * 36 + c], xs[(9 + 2 * tg) * 577 + (g + 8) * 36 + c]);
    size_t dst = (size_t)(c0 + c) * 65536 + (size_t)blockIdx.z * 2048 +
                 (size_t)blockIdx.y * 256 + lane * 8;
    *(uint4*)(g_packed + dst) = v;
  }
}

// ------------------------------------------------------------------ pass 2
// Hybrid: 20 HMMA warps (n in [0,160), 32m x 32n each, 5 per SMSP) +
//          4 FFMA warps (n in [160,192), 8 cols each, 1 per SMSP).
#define ATILEB 8192                 // 2 ks16 x 8 mtiles x 32 lanes x 16B (fp16 frags)
#define BTILEB (FF * 144)           // 192 rows x 36 floats pitch = 27648 B (fp32)
#define STAGEB (ATILEB + BTILEB)    // 35840 B
#define NSTG 4
#define NTHR 768
#define SCRW 132                    // fp32 A scratch row pitch (floats)
#define SCRB (32 * SCRW * 4)        // 16896 B per scratch buffer
#define DYNSM (NSTG * STAGEB + 2 * SCRB + (FF + BB) * 4)

static __device__ __forceinline__ void prefetch_stage(
    uint32_t sbase, int s, int t, const __half* __restrict__ Ag, const float* __restrict__ Wg) {
  uint32_t ab = sbase + (uint32_t)((s % NSTG) * STAGEB);
  const __half* asrc = Ag + (size_t)s * 4096;
  if (t < 512) {                     // 512 x 16B (A tile)
    cp16(ab + t * 16, asrc + t * 8);
  }
  uint32_t bb2 = ab + ATILEB;
  const float* bsrc = Wg + s * 32;
#pragma unroll
  for (int i = 0; i < 2; i++) {      // 1536 = 192 rows * 8 segs
    int id = t + NTHR * i;
    int f = id >> 3, sg = id & 7;
    cp16(bb2 + f * 144 + sg * 16, bsrc + (size_t)f * LL + sg * 4);
  }
}

__global__ void __launch_bounds__(NTHR, 1) gemm_kernel(
    const float* __restrict__ W, const float* __restrict__ bias,
    const float* __restrict__ x, int c_base) {
  extern __shared__ char smc[];
  char*  stg    = smc;
  float* scr0   = (float*)(smc + NSTG * STAGEB);          // 2 x fp32 A scratch
  float* s_bias = (float*)(smc + NSTG * STAGEB + 2 * SCRB);
  float* s_norm = s_bias + FF;

  const int t = threadIdx.x;
  const int c = c_base + blockIdx.x;
  const int wid = t >> 5, lane = t & 31;
  const int g = lane >> 2, tg = lane & 3;
  const uint32_t sbase = smem_u32(smc);

  for (int i = t; i < FF; i += NTHR) s_bias[i] = bias[(size_t)c * FF + i];
  for (int i = t; i < BB; i += NTHR) s_norm[i] = x[((size_t)i * LL + (LL - 1)) * CC + c];

  const __half* Ag = g_packed + (size_t)c * 65536;
  const float*  Wg = W + (size_t)c * (FF * LL);
  float* outp = g_outp + (size_t)c * (BB * FF);

  // HMMA identity: m-quarter mq, n-slice ns; FFMA identity: octet o
  const int mq = wid / 5, ns = wid - mq * 5;   // valid for wid < 20
  const int o  = wid - 20;                     // valid for wid >= 20

  float d[2][4][4];                            // HMMA acc (32m x 32n)
  float facc[4][8];                            // FFMA acc (4m x 8n)
#pragma unroll
  for (int a = 0; a < 2; a++)
#pragma unroll
    for (int b = 0; b < 4; b++)
#pragma unroll
      for (int r = 0; r < 4; r++) d[a][b][r] = 0.f;
#pragma unroll
  for (int a = 0; a < 4; a++)
#pragma unroll
    for (int b = 0; b < 8; b++) facc[a][b] = 0.f;

  prefetch_stage(sbase, 0, t, Ag, Wg);
  asm volatile("cp.async.commit_group;" ::: "memory");
  prefetch_stage(sbase, 1, t, Ag, Wg);
  asm volatile("cp.async.commit_group;" ::: "memory");
  prefetch_stage(sbase, 2, t, Ag, Wg);
  asm volatile("cp.async.commit_group;" ::: "memory");

  for (int s = 0; s < 16; s++) {
    asm volatile("cp.async.wait_group 2;" ::: "memory");
    __syncthreads();
    if (s + 3 < 16) prefetch_stage(sbase, s + 3, t, Ag, Wg);
    asm volatile("cp.async.commit_group;" ::: "memory");

    const __half* As = (const __half*)(stg + (size_t)(s % NSTG) * STAGEB);
    const float*  Bs = (const float*)(stg + (size_t)(s % NSTG) * STAGEB + ATILEB);

    if (wid < 20) {
      // ---------------- HMMA: 32m x 32n per warp ----------------
#pragma unroll
      for (int ks = 0; ks < 2; ks++) {
        uint4 a[2];
#pragma unroll
        for (int wm = 0; wm < 2; wm++)
          a[wm] = *(const uint4*)(As + ((size_t)((ks * 8 + mq * 2 + wm) * 32 + lane)) * 8);
        uint32_t b0[4], b1[4];
#pragma unroll
        for (int j = 0; j < 4; j++) {
          const float* bp = Bs + (ns * 32 + j * 8 + g) * 36 + ks * 16;
          float2 lo = *(const float2*)(bp + 2 * tg);
          float2 hi = *(const float2*)(bp + 8 + 2 * tg);
          b0[j] = pk2(lo.x, lo.y);
          b1[j] = pk2(hi.x, hi.y);
        }
#pragma unroll
        for (int wm = 0; wm < 2; wm++)
#pragma unroll
          for (int j = 0; j < 4; j++) mma16(d[wm][j], a[wm], b0[j], b1[j]);
      }
    } else {
      // ---------------- FFMA: n in [160+8o, 160+8o+8) ----------------
      float* SCR = scr0 + (s & 1) * (SCRB / 4);
      // Cooperative convert: this warp handles mtiles {2o, 2o+1}, both ks.
#pragma unroll
      for (int ks = 0; ks < 2; ks++)
#pragma unroll
        for (int mi = 0; mi < 2; mi++) {
          int mt = 2 * o + mi;
          uint4 af = *(const uint4*)(As + ((size_t)((ks * 8 + mt) * 32 + lane)) * 8);
          int k0 = ks * 16 + 2 * tg;
          int mA = mt * 16 + g;
          float2 fx = __half22float2(*(__half2*)&af.x);  // (k0,mA),(k0+1,mA)
          float2 fy = __half22float2(*(__half2*)&af.y);  // m+8
          float2 fz = __half22float2(*(__half2*)&af.z);  // k0+8
          float2 fw = __half22float2(*(__half2*)&af.w);  // k0+8, m+8
          SCR[k0 * SCRW + mA]           = fx.x;
          SCR[(k0 + 1) * SCRW + mA]     = fx.y;
          SCR[k0 * SCRW + mA + 8]       = fy.x;
          SCR[(k0 + 1) * SCRW + mA + 8] = fy.y;
          SCR[(k0 + 8) * SCRW + mA]         = fz.x;
          SCR[(k0 + 9) * SCRW + mA]         = fz.y;
          SCR[(k0 + 8) * SCRW + mA + 8]     = fw.x;
          SCR[(k0 + 9) * SCRW + mA + 8]     = fw.y;
        }
      asm volatile("bar.sync 1, 128;" ::: "memory");
      // Compute: thread owns m = 4*lane .. 4*lane+3
      const float* Wr = Bs + (160 + o * 8) * 36;
#pragma unroll 4
      for (int kp = 0; kp < 16; kp++) {
        int k = 2 * kp;
        float4 a0 = *(const float4*)(SCR + k * SCRW + 4 * lane);
        float4 a1 = *(const float4*)(SCR + (k + 1) * SCRW + 4 * lane);
#pragma unroll
        for (int j = 0; j < 8; j++) {
          float2 w = *(const float2*)(Wr + j * 36 + k);
          facc[0][j] += a0.x * w.x + a1.x * w.y;
          facc[1][j] += a0.y * w.x + a1.y * w.y;
          facc[2][j] += a0.z * w.x + a1.z * w.y;
          facc[3][j] += a0.w * w.x + a1.w * w.y;
        }
      }
    }
  }

  // ---------------- epilogue ----------------
  if (wid < 20) {
#pragma unroll
    for (int wm = 0; wm < 2; wm++) {
      int m0 = mq * 32 + wm * 16 + g;
      float nlo = s_norm[m0], nhi = s_norm[m0 + 8];
#pragma unroll
      for (int j = 0; j < 4; j++) {
        int n = ns * 32 + j * 8 + 2 * tg;
        float bx = s_bias[n], by = s_bias[n + 1];
        float2 lo = make_float2(d[wm][j][0] + bx + nlo, d[wm][j][1] + by + nlo);
        float2 hi = make_float2(d[wm][j][2] + bx + nhi, d[wm][j][3] + by + nhi);
        *(float2*)(outp + (size_t)m0 * FF + n)       = lo;
        *(float2*)(outp + (size_t)(m0 + 8) * FF + n) = hi;
      }
    }
  } else {
#pragma unroll
    for (int i = 0; i < 4; i++) {
      int m = 4 * lane + i;
      float nm = s_norm[m];
#pragma unroll
      for (int j = 0; j < 4; j++) {
        int n = 160 + o * 8 + 2 * j;
        float2 v = make_float2(facc[i][2 * j] + s_bias[n] + nm,
                               facc[i][2 * j + 1] + s_bias[n + 1] + nm);
        *(float2*)(outp + (size_t)m * FF + n) = v;
      }
    }
  }
}

// ------------------------------------------------------------------ pass 3
// transpose g_outp [c][b*f] -> out [b*f][c]; tile 32c x 128bf
__global__ void __launch_bounds__(256) transpose_kernel(float* __restrict__ out, int c_base) {
  __shared__ float ts[32 * 132];
  const int t   = threadIdx.x;
  const int bf0 = blockIdx.x * 128;
  const int c0  = c_base + blockIdx.y * 32;
#pragma unroll
  for (int i = 0; i < 4; i++) {
    int id = t + 256 * i;
    int cr = id >> 5, sg = id & 31;
    float4 v = *(const float4*)(g_outp + (size_t)(c0 + cr) * (BB * FF) + bf0 + sg * 4);
    *(float4*)&ts[cr * 132 + sg * 4] = v;
  }
  __syncthreads();
#pragma unroll
  for (int i = 0; i < 4; i++) {
    int id = t + 256 * i;
    int r = id >> 3, sg = id & 7;
    float4 v;
    v.x = ts[(sg * 4 + 0) * 132 + r];
    v.y = ts[(sg * 4 + 1) * 132 + r];
    v.z = ts[(sg * 4 + 2) * 132 + r];
    v.w = ts[(sg * 4 + 3) * 132 + r];
    *(float4*)(out + (size_t)(bf0 + r) * CC + c0 + sg * 4) = v;
  }
}

// ------------------------------------------------------------------ launch
// R12 schedule: graded slabs {64,64,128,128,64,64}; gemms alternate s0/sB;
// packs on s1, transposes on s2.
#define NSLAB 6
static const int slab_base[NSLAB] = {0, 64, 128, 256, 384, 448};
static const int slab_size[NSLAB] = {64, 64, 128, 128, 64, 64};

extern "C" void kernel_launch(void* const* d_in, const int* in_sizes, int n_in,
                              void* d_out, int out_size) {
  const float* x    = (const float*)d_in[0];
  const float* W    = (const float*)d_in[1];
  const float* bias = (const float*)d_in[2];
  float* out        = (float*)d_out;
  (void)in_sizes; (void)n_in; (void)out_size;

  static cudaStream_t s1 = nullptr, s2 = nullptr, sB = nullptr;
  static cudaEvent_t ev_fork, ev_pack[NSLAB], ev_gemm[NSLAB], ev_join;
  if (s1 == nullptr) {
    cudaStreamCreateWithFlags(&s1, cudaStreamNonBlocking);
    cudaStreamCreateWithFlags(&s2, cudaStreamNonBlocking);
    cudaStreamCreateWithFlags(&sB, cudaStreamNonBlocking);
    cudaEventCreateWithFlags(&ev_fork, cudaEventDisableTiming);
    for (int i = 0; i < NSLAB; i++) {
      cudaEventCreateWithFlags(&ev_pack[i], cudaEventDisableTiming);
      cudaEventCreateWithFlags(&ev_gemm[i], cudaEventDisableTiming);
    }
    cudaEventCreateWithFlags(&ev_join, cudaEventDisableTiming);
  }

  cudaFuncSetAttribute(gemm_kernel, cudaFuncAttributeMaxDynamicSharedMemorySize, DYNSM);

  cudaStream_t s0 = (cudaStream_t)0;   // legacy default stream (capture origin)

  cudaEventRecord(ev_fork, s0);
  cudaStreamWaitEvent(s1, ev_fork, 0);
  cudaStreamWaitEvent(s2, ev_fork, 0);
  cudaStreamWaitEvent(sB, ev_fork, 0);

  for (int i = 0; i < NSLAB; i++) {
    pack_kernel<<<dim3(slab_size[i] / 32, BB / 16, LL / 16), 256, 0, s1>>>(x, slab_base[i]);
    cudaEventRecord(ev_pack[i], s1);
  }

  for (int i = 0; i < NSLAB; i++) {
    cudaStream_t sg = (i & 1) ? sB : s0;
    cudaStreamWaitEvent(sg, ev_pack[i], 0);
    gemm_kernel<<<slab_size[i], NTHR, DYNSM, sg>>>(W, bias, x, slab_base[i]);
    cudaEventRecord(ev_gemm[i], sg);
  }

  for (int i = 0; i < NSLAB; i++) {
    cudaStreamWaitEvent(s2, ev_gemm[i], 0);
    transpose_kernel<<<dim3(BB * FF / 128, slab_size[i] / 32), 256, 0, s2>>>(out, slab_base[i]);
  }
  cudaEventRecord(ev_join, s2);

  cudaStreamWaitEvent(s0, ev_join, 0);
}

// round 14
// speedup vs baseline: 2.8335x; 2.8335x over previous
#include <cuda_runtime.h>
#include <cuda_fp16.h>
#include <cstdint>

#define BB 128   // batch    (GEMM M)
#define LL 512   // lookback (GEMM K)
#define CC 512   // channels
#define FF 192   // forecast (GEMM N)

// A (nx = x - norm) in fp16 mma-fragment order:
// [c][ks16(32)][mtile(8)][lane(32)][8 halves]  -> 128KB/channel
__device__ __half g_packed[(size_t)CC * BB * LL];
// GEMM output staged coalesced per channel: [c][b][f]
__device__ float g_outp[(size_t)CC * BB * FF];

// ------------------------------------------------------------------ helpers
static __device__ __forceinline__ uint32_t smem_u32(const void* p) {
  uint32_t a;
  asm("{ .reg .u64 t; cvta.to.shared.u64 t, %1; cvt.u32.u64 %0, t; }" : "=r"(a) : "l"(p));
  return a;
}
static __device__ __forceinline__ void cp16(uint32_t dst, const void* src) {
  asm volatile("cp.async.cg.shared.global [%0], [%1], 16;" :: "r"(dst), "l"(src) : "memory");
}
// pack two floats into f16x2 (lo = first arg)
static __device__ __forceinline__ uint32_t pk2(float lo, float hi) {
  uint32_t r;
  asm("cvt.rn.f16x2.f32 %0, %1, %2;" : "=r"(r) : "f"(hi), "f"(lo));
  return r;
}
static __device__ __forceinline__ void mma16(float* d, const uint4& a, uint32_t b0, uint32_t b1) {
  asm volatile(
      "mma.sync.aligned.m16n8k16.row.col.f32.f16.f16.f32 "
      "{%0,%1,%2,%3}, {%4,%5,%6,%7}, {%8,%9}, {%0,%1,%2,%3};"
      : "+f"(d[0]), "+f"(d[1]), "+f"(d[2]), "+f"(d[3])
      : "r"(a.x), "r"(a.y), "r"(a.z), "r"(a.w), "r"(b0), "r"(b1));
}

// ------------------------------------------------------------------ pass 1
// m16n8k16 A-fragment: a0=(g, 2tg..2tg+1), a1=(g+8, 2tg..), a2=(g, 8+2tg..),
// a3=(g+8, 8+2tg..); lane = g*4+tg. Tile: 32 ch x 16 batch x 16 lookback.
__global__ void __launch_bounds__(256) pack_kernel(const float* __restrict__ x, int c_base) {
  __shared__ float xs[15 * 577 + 15 * 36 + 32 + 1];  // [l]*577 + [b]*36 + c
  __shared__ float nrm[16][32];
  const int t  = threadIdx.x;
  const int c0 = c_base + blockIdx.x * 32;
  const int b0 = blockIdx.y * 16;
  const int l0 = blockIdx.z * 16;

  if (t < 128) {
    int b = t >> 3, sg = t & 7;
    float4 v = *(const float4*)(x + ((size_t)(b0 + b) * LL + (LL - 1)) * CC + c0 + sg * 4);
    *(float4*)&nrm[b][sg * 4] = v;
  }
  __syncthreads();

#pragma unroll
  for (int i = 0; i < 8; i++) {
    int id = t + 256 * i;
    int row = id >> 3, sg = id & 7;
    int b = row >> 4, l = row & 15;
    float4 v = *(const float4*)(x + ((size_t)(b0 + b) * LL + l0 + l) * CC + c0 + sg * 4);
    float4 n = *(float4*)&nrm[b][sg * 4];
    int base = l * 577 + b * 36 + sg * 4;
    xs[base + 0] = v.x - n.x;
    xs[base + 1] = v.y - n.y;
    xs[base + 2] = v.z - n.z;
    xs[base + 3] = v.w - n.w;
  }
  __syncthreads();

  const int wid = t >> 5, lane = t & 31;
  const int g = lane >> 2, tg = lane & 3;
#pragma unroll
  for (int it = 0; it < 4; it++) {
    int c = wid * 4 + it;
    uint4 v;
    v.x = pk2(xs[(2 * tg)     * 577 + g       * 36 + c], xs[(2 * tg + 1) * 577 + g       * 36 + c]);
    v.y = pk2(xs[(2 * tg)     * 577 + (g + 8) * 36 + c], xs[(2 * tg + 1) * 577 + (g + 8) * 36 + c]);
    v.z = pk2(xs[(8 + 2 * tg) * 577 + g       * 36 + c], xs[(9 + 2 * tg) * 577 + g       * 36 + c]);
    v.w = pk2(xs[(8 + 2 * tg) * 577 + (g + 8) * 36 + c], xs[(9 + 2 * tg) * 577 + (g + 8) * 36 + c]);
    size_t dst = (size_t)(c0 + c) * 65536 + (size_t)blockIdx.z * 2048 +
                 (size_t)blockIdx.y * 256 + lane * 8;
    *(uint4*)(g_packed + dst) = v;
  }
}

// ------------------------------------------------------------------ pass 2 (512thr, NSTG=5)
#define ATILEB 8192                 // 2 ks16 x 8 mtiles x 32 lanes x 16B (fp16 frags)
#define BTILEB (FF * 144)           // 192 rows x 36 floats pitch = 27648 B (fp32)
#define STAGEB (ATILEB + BTILEB)    // 35840 B
#define NSTG 5
#define NTHR 512
#define DYNSM (NSTG * STAGEB + (FF + BB) * 4)

static __device__ __forceinline__ void prefetch_stage(
    uint32_t sbase, int s, int t, const __half* __restrict__ Ag, const float* __restrict__ Wg) {
  uint32_t ab = sbase + (uint32_t)((s % NSTG) * STAGEB);
  const __half* asrc = Ag + (size_t)s * 4096;
  {  // 512 x 16B
    cp16(ab + t * 16, asrc + t * 8);
  }
  uint32_t bb2 = ab + ATILEB;
  const float* bsrc = Wg + s * 32;
#pragma unroll
  for (int i = 0; i < 3; i++) {      // 1536 = 192 rows * 8 segs
    int id = t + NTHR * i;
    int f = id >> 3, sg = id & 7;
    cp16(bb2 + f * 144 + sg * 16, bsrc + (size_t)f * LL + sg * 4);
  }
}

__global__ void __launch_bounds__(NTHR, 1) gemm_kernel(
    const float* __restrict__ W, const float* __restrict__ bias,
    const float* __restrict__ x, int c_base) {
  extern __shared__ char smc[];
  char*  stg    = smc;
  float* s_bias = (float*)(smc + NSTG * STAGEB);
  float* s_norm = s_bias + FF;

  const int t = threadIdx.x;
  const int c = c_base + blockIdx.x;
  const int wid = t >> 5, lane = t & 31;
  const int g = lane >> 2, tg = lane & 3;
  const int wr = wid >> 3, wn = wid & 7;   // 2 M-halves x 8 N-slices (64m x 24n)
  const uint32_t sbase = smem_u32(smc);

  for (int i = t; i < FF; i += NTHR) s_bias[i] = bias[(size_t)c * FF + i];
  for (int i = t; i < BB; i += NTHR) s_norm[i] = x[((size_t)i * LL + (LL - 1)) * CC + c];

  const __half* Ag = g_packed + (size_t)c * 65536;
  const float*  Wg = W + (size_t)c * (FF * LL);

  float d[4][3][4];
#pragma unroll
  for (int a = 0; a < 4; a++)
#pragma unroll
    for (int b = 0; b < 3; b++)
#pragma unroll
      for (int r = 0; r < 4; r++) d[a][b][r] = 0.f;

  prefetch_stage(sbase, 0, t, Ag, Wg);
  asm volatile("cp.async.commit_group;" ::: "memory");
  prefetch_stage(sbase, 1, t, Ag, Wg);
  asm volatile("cp.async.commit_group;" ::: "memory");
  prefetch_stage(sbase, 2, t, Ag, Wg);
  asm volatile("cp.async.commit_group;" ::: "memory");
  prefetch_stage(sbase, 3, t, Ag, Wg);
  asm volatile("cp.async.commit_group;" ::: "memory");

  for (int s = 0; s < 16; s++) {
    asm volatile("cp.async.wait_group 3;" ::: "memory");
    __syncthreads();
    if (s + 4 < 16) prefetch_stage(sbase, s + 4, t, Ag, Wg);
    asm volatile("cp.async.commit_group;" ::: "memory");

    const __half* As = (const __half*)(stg + (size_t)(s % NSTG) * STAGEB);
    const float*  Bs = (const float*)(stg + (size_t)(s % NSTG) * STAGEB + ATILEB);
#pragma unroll
    for (int ks = 0; ks < 2; ks++) {   // two k16 steps per 32-K stage
      uint4 a[4];
#pragma unroll
      for (int wm = 0; wm < 4; wm++)
        a[wm] = *(const uint4*)(As + ((size_t)((ks * 8 + wr * 4 + wm) * 32 + lane)) * 8);
      uint32_t b0[3], b1[3];
#pragma unroll
      for (int j = 0; j < 3; j++) {
        const float* bp = Bs + (wn * 24 + j * 8 + g) * 36 + ks * 16;
        float2 lo = *(const float2*)(bp + 2 * tg);
        float2 hi = *(const float2*)(bp + 8 + 2 * tg);
        b0[j] = pk2(lo.x, lo.y);
        b1[j] = pk2(hi.x, hi.y);
      }
#pragma unroll
      for (int wm = 0; wm < 4; wm++)
#pragma unroll
        for (int j = 0; j < 3; j++) mma16(d[wm][j], a[wm], b0[j], b1[j]);
    }
  }

  // epilogue: out_packed[c][m][n] = acc + bias[n] + norm[m], coalesced STG.64
  float* outp = g_outp + (size_t)c * (BB * FF);
#pragma unroll
  for (int wm = 0; wm < 4; wm++) {
    int m0 = wr * 64 + wm * 16 + g;
    float nlo = s_norm[m0], nhi = s_norm[m0 + 8];
#pragma unroll
    for (int j = 0; j < 3; j++) {
      int n = wn * 24 + j * 8 + 2 * tg;
      float bx = s_bias[n], by = s_bias[n + 1];
      float2 lo = make_float2(d[wm][j][0] + bx + nlo, d[wm][j][1] + by + nlo);
      float2 hi = make_float2(d[wm][j][2] + bx + nhi, d[wm][j][3] + by + nhi);
      *(float2*)(outp + (size_t)m0 * FF + n)       = lo;
      *(float2*)(outp + (size_t)(m0 + 8) * FF + n) = hi;
    }
  }
}

// ------------------------------------------------------------------ pass 3
// transpose g_outp [c][b*f] -> out [b*f][c]; tile 32c x 128bf
__global__ void __launch_bounds__(256) transpose_kernel(float* __restrict__ out, int c_base) {
  __shared__ float ts[32 * 132];
  const int t   = threadIdx.x;
  const int bf0 = blockIdx.x * 128;
  const int c0  = c_base + blockIdx.y * 32;
#pragma unroll
  for (int i = 0; i < 4; i++) {
    int id = t + 256 * i;
    int cr = id >> 5, sg = id & 31;
    float4 v = *(const float4*)(g_outp + (size_t)(c0 + cr) * (BB * FF) + bf0 + sg * 4);
    *(float4*)&ts[cr * 132 + sg * 4] = v;
  }
  __syncthreads();
#pragma unroll
  for (int i = 0; i < 4; i++) {
    int id = t + 256 * i;
    int r = id >> 3, sg = id & 7;
    float4 v;
    v.x = ts[(sg * 4 + 0) * 132 + r];
    v.y = ts[(sg * 4 + 1) * 132 + r];
    v.z = ts[(sg * 4 + 2) * 132 + r];
    v.w = ts[(sg * 4 + 3) * 132 + r];
    *(float4*)(out + (size_t)(bf0 + r) * CC + c0 + sg * 4) = v;
  }
}

// ------------------------------------------------------------------ launch
// R12 schedule: graded slabs {64,64,128,128,64,64}; gemms alternate s0/sB;
// packs on s1, transposes on s2.
#define NSLAB 6
static const int slab_base[NSLAB] = {0, 64, 128, 256, 384, 448};
static const int slab_size[NSLAB] = {64, 64, 128, 128, 64, 64};

extern "C" void kernel_launch(void* const* d_in, const int* in_sizes, int n_in,
                              void* d_out, int out_size) {
  const float* x    = (const float*)d_in[0];
  const float* W    = (const float*)d_in[1];
  const float* bias = (const float*)d_in[2];
  float* out        = (float*)d_out;
  (void)in_sizes; (void)n_in; (void)out_size;

  static cudaStream_t s1 = nullptr, s2 = nullptr, sB = nullptr;
  static cudaEvent_t ev_fork, ev_pack[NSLAB], ev_gemm[NSLAB], ev_join;
  if (s1 == nullptr) {
    cudaStreamCreateWithFlags(&s1, cudaStreamNonBlocking);
    cudaStreamCreateWithFlags(&s2, cudaStreamNonBlocking);
    cudaStreamCreateWithFlags(&sB, cudaStreamNonBlocking);
    cudaEventCreateWithFlags(&ev_fork, cudaEventDisableTiming);
    for (int i = 0; i < NSLAB; i++) {
      cudaEventCreateWithFlags(&ev_pack[i], cudaEventDisableTiming);
      cudaEventCreateWithFlags(&ev_gemm[i], cudaEventDisableTiming);
    }
    cudaEventCreateWithFlags(&ev_join, cudaEventDisableTiming);
  }

  cudaFuncSetAttribute(gemm_kernel, cudaFuncAttributeMaxDynamicSharedMemorySize, DYNSM);

  cudaStream_t s0 = (cudaStream_t)0;   // legacy default stream (capture origin)

  cudaEventRecord(ev_fork, s0);
  cudaStreamWaitEvent(s1, ev_fork, 0);
  cudaStreamWaitEvent(s2, ev_fork, 0);
  cudaStreamWaitEvent(sB, ev_fork, 0);

  for (int i = 0; i < NSLAB; i++) {
    pack_kernel<<<dim3(slab_size[i] / 32, BB / 16, LL / 16), 256, 0, s1>>>(x, slab_base[i]);
    cudaEventRecord(ev_pack[i], s1);
  }

  for (int i = 0; i < NSLAB; i++) {
    cudaStream_t sg = (i & 1) ? sB : s0;
    cudaStreamWaitEvent(sg, ev_pack[i], 0);
    gemm_kernel<<<slab_size[i], NTHR, DYNSM, sg>>>(W, bias, x, slab_base[i]);
    cudaEventRecord(ev_gemm[i], sg);
  }

  for (int i = 0; i < NSLAB; i++) {
    cudaStreamWaitEvent(s2, ev_gemm[i], 0);
    transpose_kernel<<<dim3(BB * FF / 128, slab_size[i] / 32), 256, 0, s2>>>(out, slab_base[i]);
  }
  cudaEventRecord(ev_join, s2);

  cudaStreamWaitEvent(s0, ev_join, 0);
}

// round 15
// speedup vs baseline: 2.8643x; 1.0109x over previous
#include <cuda_runtime.h>
#include <cuda_fp16.h>
#include <cstdint>

#define BB 128   // batch    (GEMM M)
#define LL 512   // lookback (GEMM K)
#define CC 512   // channels
#define FF 192   // forecast (GEMM N)

// A (nx = x - norm) in fp16 mma-fragment order:
// [c][ks16(32)][mtile(8)][lane(32)][8 halves]  -> 128KB/channel
__device__ __half g_packed[(size_t)CC * BB * LL];
// GEMM output staged coalesced per channel: [c][b][f]
__device__ float g_outp[(size_t)CC * BB * FF];

// ------------------------------------------------------------------ helpers
static __device__ __forceinline__ uint32_t smem_u32(const void* p) {
  uint32_t a;
  asm("{ .reg .u64 t; cvta.to.shared.u64 t, %1; cvt.u32.u64 %0, t; }" : "=r"(a) : "l"(p));
  return a;
}
static __device__ __forceinline__ void cp16(uint32_t dst, const void* src) {
  asm volatile("cp.async.cg.shared.global [%0], [%1], 16;" :: "r"(dst), "l"(src) : "memory");
}
// pack two floats into f16x2 (lo = first arg)
static __device__ __forceinline__ uint32_t pk2(float lo, float hi) {
  uint32_t r;
  asm("cvt.rn.f16x2.f32 %0, %1, %2;" : "=r"(r) : "f"(hi), "f"(lo));
  return r;
}
static __device__ __forceinline__ void mma16(float* d, const uint4& a, uint32_t b0, uint32_t b1) {
  asm volatile(
      "mma.sync.aligned.m16n8k16.row.col.f32.f16.f16.f32 "
      "{%0,%1,%2,%3}, {%4,%5,%6,%7}, {%8,%9}, {%0,%1,%2,%3};"
      : "+f"(d[0]), "+f"(d[1]), "+f"(d[2]), "+f"(d[3])
      : "r"(a.x), "r"(a.y), "r"(a.z), "r"(a.w), "r"(b0), "r"(b1));
}

// ------------------------------------------------------------------ pass 1
// m16n8k16 A-fragment: a0=(g, 2tg..2tg+1), a1=(g+8, 2tg..), a2=(g, 8+2tg..),
// a3=(g+8, 8+2tg..); lane = g*4+tg. Tile: 32 ch x 16 batch x 16 lookback.
__global__ void __launch_bounds__(256) pack_kernel(const float* __restrict__ x, int c_base) {
  __shared__ float xs[15 * 577 + 15 * 36 + 32 + 1];  // [l]*577 + [b]*36 + c
  __shared__ float nrm[16][32];
  const int t  = threadIdx.x;
  const int c0 = c_base + blockIdx.x * 32;
  const int b0 = blockIdx.y * 16;
  const int l0 = blockIdx.z * 16;

  if (t < 128) {
    int b = t >> 3, sg = t & 7;
    float4 v = *(const float4*)(x + ((size_t)(b0 + b) * LL + (LL - 1)) * CC + c0 + sg * 4);
    *(float4*)&nrm[b][sg * 4] = v;
  }
  __syncthreads();

#pragma unroll
  for (int i = 0; i < 8; i++) {
    int id = t + 256 * i;
    int row = id >> 3, sg = id & 7;
    int b = row >> 4, l = row & 15;
    float4 v = *(const float4*)(x + ((size_t)(b0 + b) * LL + l0 + l) * CC + c0 + sg * 4);
    float4 n = *(float4*)&nrm[b][sg * 4];
    int base = l * 577 + b * 36 + sg * 4;
    xs[base + 0] = v.x - n.x;
    xs[base + 1] = v.y - n.y;
    xs[base + 2] = v.z - n.z;
    xs[base + 3] = v.w - n.w;
  }
  __syncthreads();

  const int wid = t >> 5, lane = t & 31;
  const int g = lane >> 2, tg = lane & 3;
#pragma unroll
  for (int it = 0; it < 4; it++) {
    int c = wid * 4 + it;
    uint4 v;
    v.x = pk2(xs[(2 * tg)     * 577 + g       * 36 + c], xs[(2 * tg + 1) * 577 + g       * 36 + c]);
    v.y = pk2(xs[(2 * tg)     * 577 + (g + 8) * 36 + c], xs[(2 * tg + 1) * 577 + (g + 8) * 36 + c]);
    v.z = pk2(xs[(8 + 2 * tg) * 577 + g       * 36 + c], xs[(9 + 2 * tg) * 577 + g       * 36 + c]);
    v.w = pk2(xs[(8 + 2 * tg) * 577 + (g + 8) * 36 + c], xs[(9 + 2 * tg) * 577 + (g + 8) * 36 + c]);
    size_t dst = (size_t)(c0 + c) * 65536 + (size_t)blockIdx.z * 2048 +
                 (size_t)blockIdx.y * 256 + lane * 8;
    *(uint4*)(g_packed + dst) = v;
  }
}

// ------------------------------------------------------------------ pass 2 (512thr, NSTG=5)
#define ATILEB 8192                 // 2 ks16 x 8 mtiles x 32 lanes x 16B (fp16 frags)
#define BTILEB (FF * 144)           // 192 rows x 36 floats pitch = 27648 B (fp32)
#define STAGEB (ATILEB + BTILEB)    // 35840 B
#define NSTG 5
#define NTHR 512
#define DYNSM (NSTG * STAGEB + (FF + BB) * 4)

static __device__ __forceinline__ void prefetch_stage(
    uint32_t sbase, int s, int t, const __half* __restrict__ Ag, const float* __restrict__ Wg) {
  uint32_t ab = sbase + (uint32_t)((s % NSTG) * STAGEB);
  const __half* asrc = Ag + (size_t)s * 4096;
  {  // 512 x 16B
    cp16(ab + t * 16, asrc + t * 8);
  }
  uint32_t bb2 = ab + ATILEB;
  const float* bsrc = Wg + s * 32;
#pragma unroll
  for (int i = 0; i < 3; i++) {      // 1536 = 192 rows * 8 segs
    int id = t + NTHR * i;
    int f = id >> 3, sg = id & 7;
    cp16(bb2 + f * 144 + sg * 16, bsrc + (size_t)f * LL + sg * 4);
  }
}

__global__ void __launch_bounds__(NTHR, 1) gemm_kernel(
    const float* __restrict__ W, const float* __restrict__ bias,
    const float* __restrict__ x, int c_base) {
  extern __shared__ char smc[];
  char*  stg    = smc;
  float* s_bias = (float*)(smc + NSTG * STAGEB);
  float* s_norm = s_bias + FF;

  const int t = threadIdx.x;
  const int c = c_base + blockIdx.x;
  const int wid = t >> 5, lane = t & 31;
  const int g = lane >> 2, tg = lane & 3;
  const int wr = wid >> 3, wn = wid & 7;   // 2 M-halves x 8 N-slices (64m x 24n)
  const uint32_t sbase = smem_u32(smc);

  for (int i = t; i < FF; i += NTHR) s_bias[i] = bias[(size_t)c * FF + i];
  for (int i = t; i < BB; i += NTHR) s_norm[i] = x[((size_t)i * LL + (LL - 1)) * CC + c];

  const __half* Ag = g_packed + (size_t)c * 65536;
  const float*  Wg = W + (size_t)c * (FF * LL);

  float d[4][3][4];
#pragma unroll
  for (int a = 0; a < 4; a++)
#pragma unroll
    for (int b = 0; b < 3; b++)
#pragma unroll
      for (int r = 0; r < 4; r++) d[a][b][r] = 0.f;

  prefetch_stage(sbase, 0, t, Ag, Wg);
  asm volatile("cp.async.commit_group;" ::: "memory");
  prefetch_stage(sbase, 1, t, Ag, Wg);
  asm volatile("cp.async.commit_group;" ::: "memory");
  prefetch_stage(sbase, 2, t, Ag, Wg);
  asm volatile("cp.async.commit_group;" ::: "memory");
  prefetch_stage(sbase, 3, t, Ag, Wg);
  asm volatile("cp.async.commit_group;" ::: "memory");

  for (int s = 0; s < 16; s++) {
    asm volatile("cp.async.wait_group 3;" ::: "memory");
    __syncthreads();
    if (s + 4 < 16) prefetch_stage(sbase, s + 4, t, Ag, Wg);
    asm volatile("cp.async.commit_group;" ::: "memory");

    const __half* As = (const __half*)(stg + (size_t)(s % NSTG) * STAGEB);
    const float*  Bs = (const float*)(stg + (size_t)(s % NSTG) * STAGEB + ATILEB);
#pragma unroll
    for (int ks = 0; ks < 2; ks++) {   // two k16 steps per 32-K stage
      uint4 a[4];
#pragma unroll
      for (int wm = 0; wm < 4; wm++)
        a[wm] = *(const uint4*)(As + ((size_t)((ks * 8 + wr * 4 + wm) * 32 + lane)) * 8);
      uint32_t b0[3], b1[3];
#pragma unroll
      for (int j = 0; j < 3; j++) {
        const float* bp = Bs + (wn * 24 + j * 8 + g) * 36 + ks * 16;
        float2 lo = *(const float2*)(bp + 2 * tg);
        float2 hi = *(const float2*)(bp + 8 + 2 * tg);
        b0[j] = pk2(lo.x, lo.y);
        b1[j] = pk2(hi.x, hi.y);
      }
#pragma unroll
      for (int wm = 0; wm < 4; wm++)
#pragma unroll
        for (int j = 0; j < 3; j++) mma16(d[wm][j], a[wm], b0[j], b1[j]);
    }
  }

  // epilogue: out_packed[c][m][n] = acc + bias[n] + norm[m], coalesced STG.64
  float* outp = g_outp + (size_t)c * (BB * FF);
#pragma unroll
  for (int wm = 0; wm < 4; wm++) {
    int m0 = wr * 64 + wm * 16 + g;
    float nlo = s_norm[m0], nhi = s_norm[m0 + 8];
#pragma unroll
    for (int j = 0; j < 3; j++) {
      int n = wn * 24 + j * 8 + 2 * tg;
      float bx = s_bias[n], by = s_bias[n + 1];
      float2 lo = make_float2(d[wm][j][0] + bx + nlo, d[wm][j][1] + by + nlo);
      float2 hi = make_float2(d[wm][j][2] + bx + nhi, d[wm][j][3] + by + nhi);
      *(float2*)(outp + (size_t)m0 * FF + n)       = lo;
      *(float2*)(outp + (size_t)(m0 + 8) * FF + n) = hi;
    }
  }
}

// ------------------------------------------------------------------ pass 3
// transpose g_outp [c][b*f] -> out [b*f][c]; tile 32c x 128bf
__global__ void __launch_bounds__(256) transpose_kernel(float* __restrict__ out, int c_base) {
  __shared__ float ts[32 * 132];
  const int t   = threadIdx.x;
  const int bf0 = blockIdx.x * 128;
  const int c0  = c_base + blockIdx.y * 32;
#pragma unroll
  for (int i = 0; i < 4; i++) {
    int id = t + 256 * i;
    int cr = id >> 5, sg = id & 31;
    float4 v = *(const float4*)(g_outp + (size_t)(c0 + cr) * (BB * FF) + bf0 + sg * 4);
    *(float4*)&ts[cr * 132 + sg * 4] = v;
  }
  __syncthreads();
#pragma unroll
  for (int i = 0; i < 4; i++) {
    int id = t + 256 * i;
    int r = id >> 3, sg = id & 7;
    float4 v;
    v.x = ts[(sg * 4 + 0) * 132 + r];
    v.y = ts[(sg * 4 + 1) * 132 + r];
    v.z = ts[(sg * 4 + 2) * 132 + r];
    v.w = ts[(sg * 4 + 3) * 132 + r];
    *(float4*)(out + (size_t)(bf0 + r) * CC + c0 + sg * 4) = v;
  }
}

// ------------------------------------------------------------------ launch
// R12 schedule: graded slabs {64,64,128,128,64,64}; gemms alternate s0/sB;
// packs on s1, transposes on s2.
#define NSLAB 6
static const int slab_base[NSLAB] = {0, 64, 128, 256, 384, 448};
static const int slab_size[NSLAB] = {64, 64, 128, 128, 64, 64};

extern "C" void kernel_launch(void* const* d_in, const int* in_sizes, int n_in,
                              void* d_out, int out_size) {
  const float* x    = (const float*)d_in[0];
  const float* W    = (const float*)d_in[1];
  const float* bias = (const float*)d_in[2];
  float* out        = (float*)d_out;
  (void)in_sizes; (void)n_in; (void)out_size;

  static cudaStream_t s1 = nullptr, s2 = nullptr, sB = nullptr;
  static cudaEvent_t ev_fork, ev_pack[NSLAB], ev_gemm[NSLAB], ev_join;
  if (s1 == nullptr) {
    cudaStreamCreateWithFlags(&s1, cudaStreamNonBlocking);
    cudaStreamCreateWithFlags(&s2, cudaStreamNonBlocking);
    cudaStreamCreateWithFlags(&sB, cudaStreamNonBlocking);
    cudaEventCreateWithFlags(&ev_fork, cudaEventDisableTiming);
    for (int i = 0; i < NSLAB; i++) {
      cudaEventCreateWithFlags(&ev_pack[i], cudaEventDisableTiming);
      cudaEventCreateWithFlags(&ev_gemm[i], cudaEventDisableTiming);
    }
    cudaEventCreateWithFlags(&ev_join, cudaEventDisableTiming);
  }

  cudaFuncSetAttribute(gemm_kernel, cudaFuncAttributeMaxDynamicSharedMemorySize, DYNSM);

  cudaStream_t s0 = (cudaStream_t)0;   // legacy default stream (capture origin)

  cudaEventRecord(ev_fork, s0);
  cudaStreamWaitEvent(s1, ev_fork, 0);
  cudaStreamWaitEvent(s2, ev_fork, 0);
  cudaStreamWaitEvent(sB, ev_fork, 0);

  for (int i = 0; i < NSLAB; i++) {
    pack_kernel<<<dim3(slab_size[i] / 32, BB / 16, LL / 16), 256, 0, s1>>>(x, slab_base[i]);
    cudaEventRecord(ev_pack[i], s1);
  }

  for (int i = 0; i < NSLAB; i++) {
    cudaStream_t sg = (i & 1) ? sB : s0;
    cudaStreamWaitEvent(sg, ev_pack[i], 0);
    gemm_kernel<<<slab_size[i], NTHR, DYNSM, sg>>>(W, bias, x, slab_base[i]);
    cudaEventRecord(ev_gemm[i], sg);
  }

  for (int i = 0; i < NSLAB; i++) {
    cudaStreamWaitEvent(s2, ev_gemm[i], 0);
    transpose_kernel<<<dim3(BB * FF / 128, slab_size[i] / 32), 256, 0, s2>>>(out, slab_base[i]);
  }
  cudaEventRecord(ev_join, s2);

  cudaStreamWaitEvent(s0, ev_join, 0);
}